// round 3
// baseline (speedup 1.0000x reference)
#include <cuda_runtime.h>
#include <cstdint>

#define NPTS   8192
#define BMAX   8
#define G      32
#define GM     (G - 1)
#define NCELLS (G * G * G)            // 32768
#define NSB    (2 * BMAX)             // 16 set-batches (set0=preds, set1=gts)
#define QT     256                    // threads per query block
#define MAXBLK 1024

// ---- scratch (device globals; no allocation) --------------------------------
__device__ float4 g_sorted[NSB * NPTS];          // sorted points, w = |p|^2
__device__ int    g_hist[NSB * NCELLS];
__device__ int    g_cellstart[NSB * (NCELLS + 1)];
__device__ int    g_offsets[NSB * NCELLS];
__device__ float  g_bbox[NSB * 12];              // o[3], w[3], inv[3], wmin
__device__ float  g_part[MAXBLK];
__device__ unsigned int g_cnt;

__device__ __forceinline__ int cell_clamp(float v, float o, float inv) {
    int c = (int)floorf((v - o) * inv);
    return min(GM, max(0, c));
}

// ==== KA: per (set,batch): bbox reduce + zero hist + fill hist ===============
__global__ void ka_bbox_hist(const float* __restrict__ preds,
                             const float* __restrict__ gts, int B) {
    const int sb  = blockIdx.x;          // set*B + b
    const int set = sb / B, b = sb % B;
    const float* P = (set == 0 ? preds : gts) + (size_t)b * 3 * NPTS;
    const int t = threadIdx.x;

    __shared__ float sred[256];
    __shared__ float bb[12];

    // bbox: per axis min & max
    float mn[3], mx[3];
#pragma unroll
    for (int a = 0; a < 3; a++) {
        float lmn = 3.4e38f, lmx = -3.4e38f;
        for (int i = t; i < NPTS; i += 256) {
            float v = P[a * NPTS + i];
            lmn = fminf(lmn, v);
            lmx = fmaxf(lmx, v);
        }
        sred[t] = lmn; __syncthreads();
        for (int s = 128; s > 0; s >>= 1) {
            if (t < s) sred[t] = fminf(sred[t], sred[t + s]);
            __syncthreads();
        }
        mn[a] = sred[0]; __syncthreads();
        sred[t] = lmx; __syncthreads();
        for (int s = 128; s > 0; s >>= 1) {
            if (t < s) sred[t] = fmaxf(sred[t], sred[t + s]);
            __syncthreads();
        }
        mx[a] = sred[0]; __syncthreads();
    }
    if (t == 0) {
        float wmin = 3.4e38f;
#pragma unroll
        for (int a = 0; a < 3; a++) {
            float w = fmaxf(mx[a] - mn[a], 1e-5f) * (1.0f / G);
            bb[a] = mn[a];
            bb[3 + a] = w;
            bb[6 + a] = 1.0f / w;
            wmin = fminf(wmin, w);
        }
        bb[9] = wmin;
#pragma unroll
        for (int k = 0; k < 10; k++) g_bbox[sb * 12 + k] = bb[k];
    }
    __syncthreads();

    // zero this sb's histogram
    int* hist = g_hist + (size_t)sb * NCELLS;
    for (int i = t; i < NCELLS; i += 256) hist[i] = 0;
    __syncthreads();

    // fill histogram
    for (int i = t; i < NPTS; i += 256) {
        float x = P[i], y = P[NPTS + i], z = P[2 * NPTS + i];
        int cx = cell_clamp(x, bb[0], bb[6]);
        int cy = cell_clamp(y, bb[1], bb[7]);
        int cz = cell_clamp(z, bb[2], bb[8]);
        atomicAdd(&hist[(cz * G + cy) * G + cx], 1);
    }
}

// ==== KB: per (set,batch): exclusive scan + scatter ==========================
__global__ void kb_scan_scatter(const float* __restrict__ preds,
                                const float* __restrict__ gts, int B) {
    const int sb  = blockIdx.x;
    const int set = sb / B, b = sb % B;
    const float* P = (set == 0 ? preds : gts) + (size_t)b * 3 * NPTS;
    const int t = threadIdx.x;

    const int* hist = g_hist + (size_t)sb * NCELLS;
    int* cs   = g_cellstart + (size_t)sb * (NCELLS + 1);
    int* offs = g_offsets + (size_t)sb * NCELLS;

    __shared__ int ssum[256];
    const int CPT = NCELLS / 256;  // 128 cells per thread
    const int first = t * CPT;

    int local = 0;
    for (int i = 0; i < CPT; i++) local += hist[first + i];
    ssum[t] = local;
    __syncthreads();
    // inclusive Hillis-Steele
    for (int off = 1; off < 256; off <<= 1) {
        int v = (t >= off) ? ssum[t - off] : 0;
        __syncthreads();
        ssum[t] += v;
        __syncthreads();
    }
    int run = ssum[t] - local;  // exclusive base
    for (int i = 0; i < CPT; i++) {
        int c = first + i;
        cs[c] = run;
        offs[c] = run;
        run += hist[c];
    }
    if (t == 255) cs[NCELLS] = run;  // == NPTS
    __syncthreads();

    // scatter (order within cell nondeterministic -> harmless: min is exact)
    float bb0 = g_bbox[sb * 12 + 0], bb1 = g_bbox[sb * 12 + 1], bb2 = g_bbox[sb * 12 + 2];
    float iv0 = g_bbox[sb * 12 + 6], iv1 = g_bbox[sb * 12 + 7], iv2 = g_bbox[sb * 12 + 8];
    float4* dst = g_sorted + (size_t)sb * NPTS;
    for (int i = t; i < NPTS; i += 256) {
        float x = P[i], y = P[NPTS + i], z = P[2 * NPTS + i];
        int cx = cell_clamp(x, bb0, iv0);
        int cy = cell_clamp(y, bb1, iv1);
        int cz = cell_clamp(z, bb2, iv2);
        int pos = atomicAdd(&offs[(cz * G + cy) * G + cx], 1);
        dst[pos] = make_float4(x, y, z, x * x + y * y + z * z);
    }
}

// ==== KC: queries -> exact NN via expanding shells; fused deterministic sum ==
__device__ __forceinline__ void scan_run(const int* __restrict__ cs,
                                         const float4* __restrict__ pts,
                                         int c0, int c1,
                                         float nx, float ny, float nz, float& m) {
    int beg = __ldg(cs + c0);
    int end = __ldg(cs + c1 + 1);
#pragma unroll 2
    for (int k = beg; k < end; k++) {
        float4 p = __ldg(pts + k);
        float d = fmaf(nx, p.x, fmaf(ny, p.y, fmaf(nz, p.z, p.w)));
        m = fminf(m, d);
    }
}

__global__ __launch_bounds__(QT)
void kc_query(const float* __restrict__ preds,
              const float* __restrict__ gts,
              float* __restrict__ out, int B) {
    const int b   = blockIdx.y;
    const int dir = blockIdx.z;
    const int t   = threadIdx.x;
    const int q   = blockIdx.x * QT + t;

    // queries from original layout; refs from the OTHER set's grid
    const float* X = (dir == 0 ? preds : gts) + (size_t)b * 3 * NPTS;
    const int sbr = (dir == 0 ? 1 : 0) * B + b;

    __shared__ float bb[10];
    if (t < 10) bb[t] = g_bbox[sbr * 12 + t];
    __syncthreads();

    const int*    cs  = g_cellstart + (size_t)sbr * (NCELLS + 1);
    const float4* pts = g_sorted + (size_t)sbr * NPTS;

    float x0 = X[q], x1 = X[NPTS + q], x2 = X[2 * NPTS + q];
    float rx = x0 * x0 + x1 * x1 + x2 * x2;
    float nx = -2.f * x0, ny = -2.f * x1, nz = -2.f * x2;

    int cx = cell_clamp(x0, bb[0], bb[6]);
    int cy = cell_clamp(x1, bb[1], bb[7]);
    int cz = cell_clamp(x2, bb[2], bb[8]);

    // gaps from point to its cell's 6 faces (negative if outside bbox -> safe)
    float gxm = x0 - (bb[0] + cx * bb[3]), gxp = (bb[0] + (cx + 1) * bb[3]) - x0;
    float gym = x1 - (bb[1] + cy * bb[4]), gyp = (bb[1] + (cy + 1) * bb[4]) - x1;
    float gzm = x2 - (bb[2] + cz * bb[5]), gzp = (bb[2] + (cz + 1) * bb[5]) - x2;
    float gap6 = fminf(fminf(fminf(gxm, gxp), fminf(gym, gyp)), fminf(gzm, gzp));
    float wmin = bb[9];

    float m = 3.4e38f;
    for (int r = 0; r <= GM; r++) {
        if (r > 0) {
            float lb = (r - 1) * wmin + gap6;
            float bd2 = m + rx;  // current best squared distance
            if (lb > 0.f && bd2 <= lb * lb) break;
        }
        int zlo = max(cz - r, 0), zhi = min(cz + r, GM);
        int ylo = max(cy - r, 0), yhi = min(cy + r, GM);
        int xlo = max(cx - r, 0), xhi = min(cx + r, GM);
        for (int z = zlo; z <= zhi; z++) {
            bool zedge = (z == cz - r) || (z == cz + r);
            int zb = z * G;
            for (int y = ylo; y <= yhi; y++) {
                bool yedge = (y == cy - r) || (y == cy + r);
                int row = (zb + y) * G;
                if (zedge || yedge) {
                    scan_run(cs, pts, row + xlo, row + xhi, nx, ny, nz, m);
                } else {
                    if (cx - r >= 0) scan_run(cs, pts, row + cx - r, row + cx - r, nx, ny, nz, m);
                    if (cx + r <= GM) scan_run(cs, pts, row + cx + r, row + cx + r, nx, ny, nz, m);
                }
            }
        }
    }

    float s = m + rx;  // exact NN squared distance for this query

    // deterministic block tree-reduction
    __shared__ float sred[QT];
    __shared__ bool  is_last;
    sred[t] = s;
    __syncthreads();
    for (int stride = QT / 2; stride > 0; stride >>= 1) {
        if (t < stride) sred[t] += sred[t + stride];
        __syncthreads();
    }

    const int nblocks = gridDim.x * gridDim.y * gridDim.z;
    if (t == 0) {
        int bid = (blockIdx.z * gridDim.y + blockIdx.y) * gridDim.x + blockIdx.x;
        g_part[bid] = sred[0];
        __threadfence();
        unsigned int r = atomicAdd(&g_cnt, 1u);
        is_last = (r == (unsigned)(nblocks - 1));
    }
    __syncthreads();

    if (is_last) {
        float v = 0.f;
        volatile float* vp = g_part;
        for (int i = t; i < nblocks; i += QT) v += vp[i];  // fixed order per thread
        sred[t] = v;
        __syncthreads();
        for (int stride = QT / 2; stride > 0; stride >>= 1) {
            if (t < stride) sred[t] += sred[t + stride];
            __syncthreads();
        }
        if (t == 0) {
            out[0] = sred[0];
            g_cnt = 0;  // reset for next graph replay
        }
    }
}

extern "C" void kernel_launch(void* const* d_in, const int* in_sizes, int n_in,
                              void* d_out, int out_size) {
    const float* preds = (const float*)d_in[0];
    const float* gts   = (const float*)d_in[1];
    float* out = (float*)d_out;
    const int B = in_sizes[0] / (3 * NPTS);  // 8 here

    ka_bbox_hist<<<2 * B, 256>>>(preds, gts, B);
    kb_scan_scatter<<<2 * B, 256>>>(preds, gts, B);
    dim3 grid(NPTS / QT, B, 2);
    kc_query<<<grid, QT>>>(preds, gts, out, B);
}

// round 4
// speedup vs baseline: 1.7047x; 1.7047x over previous
#include <cuda_runtime.h>
#include <cstdint>

#define NPTS   8192
#define BMAX   8
#define G      16
#define GM     (G - 1)
#define NCELLS (G * G * G)            // 4096
#define NSB    (2 * BMAX)             // 16 set-batches (set0=preds, set1=gts)
#define QT     256
#define MAXBLK 1024

// ---- scratch (device globals; no allocation) --------------------------------
__device__ float4       g_sorted[NSB * NPTS];        // cell-sorted points, w=|p|^2
__device__ int          g_hist[NSB * NCELLS];
__device__ int          g_cellstart[NSB * (NCELLS + 1)];
__device__ int          g_offsets[NSB * NCELLS];
__device__ unsigned int g_bboxEnc[NSB * 6];          // enc(min xyz), enc(max xyz)
__device__ float        g_part[MAXBLK];
__device__ unsigned int g_cnt;

// monotonic float<->uint encoding for atomicMin/Max
__device__ __forceinline__ unsigned int fenc(float f) {
    unsigned int u = __float_as_uint(f);
    return (u & 0x80000000u) ? ~u : (u | 0x80000000u);
}
__device__ __forceinline__ float fdec(unsigned int u) {
    return __uint_as_float((u & 0x80000000u) ? (u ^ 0x80000000u) : ~u);
}

__device__ __forceinline__ int cell_clamp(float v, float o, float inv) {
    int c = (int)floorf((v - o) * inv);
    return min(GM, max(0, c));
}

// decode bbox params for set-batch sb into bb[10]: o[3], w[3], inv[3], wmin
__device__ __forceinline__ void decode_bbox(int sb, float* bb) {
    float wmin = 3.4e38f;
#pragma unroll
    for (int a = 0; a < 3; a++) {
        float mn = fdec(g_bboxEnc[sb * 6 + a]);
        float mx = fdec(g_bboxEnc[sb * 6 + 3 + a]);
        float w  = fmaxf(mx - mn, 1e-5f) * (1.0f / G);
        bb[a] = mn; bb[3 + a] = w; bb[6 + a] = 1.0f / w;
        wmin = fminf(wmin, w);
    }
    bb[9] = wmin;
}

__device__ __forceinline__ const float* set_base(const float* preds,
                                                 const float* gts,
                                                 int sb, int B) {
    int set = sb / B, b = sb % B;
    return (set == 0 ? preds : gts) + (size_t)b * 3 * NPTS;
}

// ==== K0: zero hist, init bbox atomics, reset counter ========================
__global__ void k0_init(int B) {
    const int sb = blockIdx.x, t = threadIdx.x;
    int* hist = g_hist + (size_t)sb * NCELLS;
    for (int i = t; i < NCELLS; i += 256) hist[i] = 0;
    if (sb == 0) {
        if (t < NSB * 6) g_bboxEnc[t] = ((t % 6) < 3) ? 0xFFFFFFFFu : 0u;
        if (t == 0) g_cnt = 0;
    }
}

// ==== K1: bbox min/max via encoded atomics (wide grid) =======================
__global__ void k1_bbox(const float* __restrict__ preds,
                        const float* __restrict__ gts, int B) {
    const int sb = blockIdx.x, chunk = blockIdx.y, t = threadIdx.x;
    const float* P = set_base(preds, gts, sb, B);
    const int CH = NPTS / 4, start = chunk * CH;

    float lmn[3] = {3.4e38f, 3.4e38f, 3.4e38f};
    float lmx[3] = {-3.4e38f, -3.4e38f, -3.4e38f};
#pragma unroll
    for (int a = 0; a < 3; a++) {
        for (int i = start + t; i < start + CH; i += 256) {
            float v = P[a * NPTS + i];
            lmn[a] = fminf(lmn[a], v);
            lmx[a] = fmaxf(lmx[a], v);
        }
    }
#pragma unroll
    for (int o = 16; o > 0; o >>= 1) {
#pragma unroll
        for (int a = 0; a < 3; a++) {
            lmn[a] = fminf(lmn[a], __shfl_xor_sync(0xffffffffu, lmn[a], o));
            lmx[a] = fmaxf(lmx[a], __shfl_xor_sync(0xffffffffu, lmx[a], o));
        }
    }
    if ((t & 31) == 0) {
#pragma unroll
        for (int a = 0; a < 3; a++) {
            atomicMin(&g_bboxEnc[sb * 6 + a],     fenc(lmn[a]));
            atomicMax(&g_bboxEnc[sb * 6 + 3 + a], fenc(lmx[a]));
        }
    }
}

// ==== K2: histogram fill ======================================================
__global__ void k2_hist(const float* __restrict__ preds,
                        const float* __restrict__ gts, int B) {
    const int sb = blockIdx.x, chunk = blockIdx.y, t = threadIdx.x;
    const float* P = set_base(preds, gts, sb, B);
    __shared__ float bb[10];
    if (t == 0) decode_bbox(sb, bb);
    __syncthreads();

    int* hist = g_hist + (size_t)sb * NCELLS;
    const int CH = NPTS / 4, start = chunk * CH;
    for (int i = start + t; i < start + CH; i += 256) {
        int cx = cell_clamp(P[i],             bb[0], bb[6]);
        int cy = cell_clamp(P[NPTS + i],      bb[1], bb[7]);
        int cz = cell_clamp(P[2 * NPTS + i],  bb[2], bb[8]);
        atomicAdd(&hist[(cz * G + cy) * G + cx], 1);
    }
}

// ==== K3: per-sb exclusive scan + scatter =====================================
__global__ void k3_scan_scatter(const float* __restrict__ preds,
                                const float* __restrict__ gts, int B) {
    const int sb = blockIdx.x, t = threadIdx.x;
    const float* P = set_base(preds, gts, sb, B);

    const int* hist = g_hist + (size_t)sb * NCELLS;
    int* cs   = g_cellstart + (size_t)sb * (NCELLS + 1);
    int* offs = g_offsets + (size_t)sb * NCELLS;

    __shared__ int   ssum[256];
    __shared__ float bb[10];
    if (t == 0) decode_bbox(sb, bb);

    const int CPT = NCELLS / 256;  // 16
    const int first = t * CPT;
    int local = 0;
#pragma unroll
    for (int i = 0; i < CPT; i++) local += hist[first + i];
    ssum[t] = local;
    __syncthreads();
    for (int off = 1; off < 256; off <<= 1) {
        int v = (t >= off) ? ssum[t - off] : 0;
        __syncthreads();
        ssum[t] += v;
        __syncthreads();
    }
    int run = ssum[t] - local;
#pragma unroll
    for (int i = 0; i < CPT; i++) {
        int c = first + i;
        cs[c] = run;
        offs[c] = run;
        run += hist[c];
    }
    if (t == 255) cs[NCELLS] = run;
    __syncthreads();

    float4* dst = g_sorted + (size_t)sb * NPTS;
    for (int i = t; i < NPTS; i += 256) {
        float x = P[i], y = P[NPTS + i], z = P[2 * NPTS + i];
        int cx = cell_clamp(x, bb[0], bb[6]);
        int cy = cell_clamp(y, bb[1], bb[7]);
        int cz = cell_clamp(z, bb[2], bb[8]);
        int pos = atomicAdd(&offs[(cz * G + cy) * G + cx], 1);
        dst[pos] = make_float4(x, y, z, x * x + y * y + z * z);
    }
}

// ==== K4: cell-sorted queries -> exact NN; fused deterministic sum ===========
__device__ __forceinline__ void scan_run(const int* __restrict__ cs,
                                         const float4* __restrict__ pts,
                                         int c0, int c1,
                                         float nx, float ny, float nz, float& m) {
    int beg = __ldg(cs + c0);
    int end = __ldg(cs + c1 + 1);
#pragma unroll 2
    for (int k = beg; k < end; k++) {
        float4 p = __ldg(pts + k);
        float d = fmaf(nx, p.x, fmaf(ny, p.y, fmaf(nz, p.z, p.w)));
        m = fminf(m, d);
    }
}

__global__ __launch_bounds__(QT)
void k4_query(float* __restrict__ out, int B) {
    const int b   = blockIdx.y;
    const int dir = blockIdx.z;
    const int t   = threadIdx.x;
    const int q   = blockIdx.x * QT + t;

    // queries read in CELL-SORTED order (warp-coherent); refs from other set
    const int sbq = (dir == 0 ? 0 : 1) * B + b;
    const int sbr = (dir == 0 ? 1 : 0) * B + b;

    __shared__ float bb[10];
    if (t == 0) decode_bbox(sbr, bb);
    __syncthreads();

    const int*    cs  = g_cellstart + (size_t)sbr * (NCELLS + 1);
    const float4* pts = g_sorted + (size_t)sbr * NPTS;

    float4 xp = __ldg(&g_sorted[(size_t)sbq * NPTS + q]);
    float x0 = xp.x, x1 = xp.y, x2 = xp.z, rx = xp.w;
    float nx = -2.f * x0, ny = -2.f * x1, nz = -2.f * x2;

    int cx = cell_clamp(x0, bb[0], bb[6]);
    int cy = cell_clamp(x1, bb[1], bb[7]);
    int cz = cell_clamp(x2, bb[2], bb[8]);

    float gxm = x0 - (bb[0] + cx * bb[3]), gxp = (bb[0] + (cx + 1) * bb[3]) - x0;
    float gym = x1 - (bb[1] + cy * bb[4]), gyp = (bb[1] + (cy + 1) * bb[4]) - x1;
    float gzm = x2 - (bb[2] + cz * bb[5]), gzp = (bb[2] + (cz + 1) * bb[5]) - x2;
    float gap6 = fminf(fminf(fminf(gxm, gxp), fminf(gym, gyp)), fminf(gzm, gzp));
    float wmin = bb[9];

    float m = 3.4e38f;
    for (int r = 0; r <= GM; r++) {
        if (r > 0) {
            float lb = (r - 1) * wmin + gap6;
            float bd2 = m + rx;
            if (lb > 0.f && bd2 <= lb * lb) break;
        }
        int zlo = max(cz - r, 0), zhi = min(cz + r, GM);
        int ylo = max(cy - r, 0), yhi = min(cy + r, GM);
        int xlo = max(cx - r, 0), xhi = min(cx + r, GM);
        for (int z = zlo; z <= zhi; z++) {
            bool zedge = (z == cz - r) || (z == cz + r);
            int zb = z * G;
            for (int y = ylo; y <= yhi; y++) {
                bool yedge = (y == cy - r) || (y == cy + r);
                int row = (zb + y) * G;
                if (zedge || yedge) {
                    scan_run(cs, pts, row + xlo, row + xhi, nx, ny, nz, m);
                } else {
                    if (cx - r >= 0)  scan_run(cs, pts, row + cx - r, row + cx - r, nx, ny, nz, m);
                    if (cx + r <= GM) scan_run(cs, pts, row + cx + r, row + cx + r, nx, ny, nz, m);
                }
            }
        }
    }

    float s = m + rx;

    // deterministic block tree-reduction + fused fixed-order final sum
    __shared__ float sred[QT];
    __shared__ bool  is_last;
    sred[t] = s;
    __syncthreads();
    for (int stride = QT / 2; stride > 0; stride >>= 1) {
        if (t < stride) sred[t] += sred[t + stride];
        __syncthreads();
    }

    const int nblocks = gridDim.x * gridDim.y * gridDim.z;
    if (t == 0) {
        int bid = (blockIdx.z * gridDim.y + blockIdx.y) * gridDim.x + blockIdx.x;
        g_part[bid] = sred[0];
        __threadfence();
        unsigned int r = atomicAdd(&g_cnt, 1u);
        is_last = (r == (unsigned)(nblocks - 1));
    }
    __syncthreads();

    if (is_last) {
        float v = 0.f;
        volatile float* vp = g_part;
        for (int i = t; i < nblocks; i += QT) v += vp[i];
        sred[t] = v;
        __syncthreads();
        for (int stride = QT / 2; stride > 0; stride >>= 1) {
            if (t < stride) sred[t] += sred[t + stride];
            __syncthreads();
        }
        if (t == 0) {
            out[0] = sred[0];
            g_cnt = 0;
        }
    }
}

extern "C" void kernel_launch(void* const* d_in, const int* in_sizes, int n_in,
                              void* d_out, int out_size) {
    const float* preds = (const float*)d_in[0];
    const float* gts   = (const float*)d_in[1];
    float* out = (float*)d_out;
    const int B = in_sizes[0] / (3 * NPTS);  // 8 here

    k0_init<<<2 * B, 256>>>(B);
    k1_bbox<<<dim3(2 * B, 4), 256>>>(preds, gts, B);
    k2_hist<<<dim3(2 * B, 4), 256>>>(preds, gts, B);
    k3_scan_scatter<<<2 * B, 256>>>(preds, gts, B);
    dim3 grid(NPTS / QT, B, 2);
    k4_query<<<grid, QT>>>(out, B);
}